// round 7
// baseline (speedup 1.0000x reference)
#include <cuda_runtime.h>
#include <cuda_bf16.h>
#include <math_constants.h>

// Problem constants
#define NPTS   8192
#define KCOMP  64
#define NB_MAX 256
#define NBLK   128           // <= 148 SMs and 1 block/SM floor -> all co-resident (no deadlock)
#define NTHR   1024
#define EPB    (NPTS / NBLK) // 64 elements per block in prep

// KDE: bw = 0.5*128/8192 = 2^-7 exactly -> exp(-8192*d^2) = exp2(CKDE*d^2)
#define LOG2E 1.4426950408889634
__device__ __constant__ float CKDE = (float)(-8192.0 * LOG2E);
__device__ __constant__ float NORM = (float)(1.0 / (2.5066282746310002 * 0.0078125 * 8192.0));
// ex2.ftz flushes to 0 for arg < -126 -> |d| > 0.10327 contributes exactly 0 in fp32.
#define HALF_R 0.052f        // bin width >= R/2; window [b-2, b+3) covers +/-R

// Scratch (device globals — no allocation allowed). All are written-then-first-read
// within the launch (L1 flushed per launch; STG doesn't allocate L1) -> plain LDG safe.
__device__ __align__(16) float g_xs[NPTS];     // counting-sorted x
__device__ float g_blkmn[NBLK], g_blkmx[NBLK];
__device__ int   g_hist[NB_MAX];
__device__ int   g_cnt[NB_MAX];                // scatter cursors (zeroed each call)
__device__ float g_coef[KCOMP], g_a[KCOMP];
__device__ float g_bsum[NBLK];
__device__ int   g_bar_cnt   = 0;              // self-resets
__device__ int   g_bar_epoch = 0;              // monotone across replays (safe)

__device__ __forceinline__ float ex2(float x) {
    float r;
    asm("ex2.approx.ftz.f32 %0, %1;" : "=f"(r) : "f"(x));
    return r;
}

// Grid-wide barrier: sense via monotone epoch. Safe because all NBLK blocks are
// co-resident (grid <= #SMs, 1 block/SM guaranteed by launch bounds).
__device__ __forceinline__ void gbar() {
    __syncthreads();
    if (threadIdx.x == 0) {
        volatile int* ep = &g_bar_epoch;
        int e = *ep;
        __threadfence();                       // release: prior writes visible
        if (atomicAdd(&g_bar_cnt, 1) == NBLK - 1) {
            atomicExch(&g_bar_cnt, 0);         // reset BEFORE flip (ordered by fence)
            __threadfence();
            atomicExch((int*)&g_bar_epoch, e + 1);
        } else {
            while (*ep == e) { }
            __threadfence();                   // acquire
        }
    }
    __syncthreads();
}

__global__ __launch_bounds__(NTHR, 1)
void gmm_fused(const float* __restrict__ x,  const float* __restrict__ wl,
               const float* __restrict__ mu, const float* __restrict__ lv,
               float* __restrict__ out) {
    __shared__ int   sbs[NB_MAX + 1];      // per-block copy of bin offsets
    __shared__ float smnK[KCOMP], scfK[KCOMP], saK[KCOMP];
    __shared__ float redm[2], redx[2];
    __shared__ float s_mn, s_invW;
    __shared__ int   s_nb;
    __shared__ float wsum[32];

    const int tid  = threadIdx.x;
    const int lane = tid & 31;
    const int w    = tid >> 5;
    const int b    = blockIdx.x;

    // ---------------- P0: slice min/max, zeroing, softmax constants ----------
    float xv = 0.0f;
    const bool have = (tid < EPB);              // threads 0..63 own one element
    if (have) xv = x[b * EPB + tid];

    if (w < 2) {                                // warps 0,1 hold the 64 elements
        float mn = xv, mx = xv;
        #pragma unroll
        for (int o = 16; o > 0; o >>= 1) {
            mn = fminf(mn, __shfl_xor_sync(0xffffffffu, mn, o));
            mx = fmaxf(mx, __shfl_xor_sync(0xffffffffu, mx, o));
        }
        if (lane == 0) { redm[w] = mn; redx[w] = mx; }
    }
    if (b == 0 && tid < NB_MAX) { g_hist[tid] = 0; g_cnt[tid] = 0; }
    if (b == 1 && tid < KCOMP) {                // softmax + per-comp constants
        float m = -CUDART_INF_F;
        #pragma unroll
        for (int i = 0; i < KCOMP; i++) m = fmaxf(m, __ldg(&wl[i]));
        float ss = 0.0f;
        #pragma unroll
        for (int i = 0; i < KCOMP; i++) ss += __expf(__ldg(&wl[i]) - m);
        float wgt = __expf(__ldg(&wl[tid]) - m) / ss;
        float var = __expf(lv[tid]);
        g_coef[tid] = wgt * rsqrtf(6.283185307179586f * var);
        g_a[tid]    = (float)(-0.5 * LOG2E) / var;
    }
    __syncthreads();
    if (tid == 0) {
        g_blkmn[b] = fminf(redm[0], redm[1]);
        g_blkmx[b] = fmaxf(redx[0], redx[1]);
    }
    gbar();  // B1

    // ------- P1: every block (warp 0) derives nb/mn/invW; then histogram -----
    if (w == 0) {
        float mn = CUDART_INF_F, mx = -CUDART_INF_F;
        #pragma unroll
        for (int q = lane; q < NBLK; q += 32) {
            mn = fminf(mn, g_blkmn[q]);
            mx = fmaxf(mx, g_blkmx[q]);
        }
        #pragma unroll
        for (int o = 16; o > 0; o >>= 1) {
            mn = fminf(mn, __shfl_xor_sync(0xffffffffu, mn, o));
            mx = fmaxf(mx, __shfl_xor_sync(0xffffffffu, mx, o));
        }
        if (lane == 0) {
            float range = mx - mn;
            int nb = (range > HALF_R) ? (int)(range / HALF_R) : 1;  // floor -> W >= R/2
            nb = min(nb, NB_MAX);
            if (nb < 1) nb = 1;
            s_nb = nb; s_mn = mn;
            s_invW = (range > 0.0f) ? (float)nb / range : 0.0f;
        }
    }
    __syncthreads();
    const int   nb   = s_nb;
    const float bmn  = s_mn;
    const float invW = s_invW;

    int mybin = 0;
    if (have) {
        mybin = (int)((xv - bmn) * invW);
        mybin = max(min(mybin, nb - 1), 0);
        atomicAdd(&g_hist[mybin], 1);
    }
    gbar();  // B2: histogram complete

    // -------- P2: per-block redundant scan of histogram; scatter -------------
    if (w == 0) {                                // warp 0: scan 256 bins
        int v[8], p[8], run = 0;
        #pragma unroll
        for (int k = 0; k < 8; k++) {
            v[k] = g_hist[lane * 8 + k];
            p[k] = run;
            run += v[k];
        }
        int incl = run;
        #pragma unroll
        for (int o = 1; o < 32; o <<= 1) {
            int u = __shfl_up_sync(0xffffffffu, incl, o);
            if (lane >= o) incl += u;
        }
        int excl = incl - run;
        #pragma unroll
        for (int k = 0; k < 8; k++) sbs[lane * 8 + k] = excl + p[k];
        if (lane == 31) sbs[NB_MAX] = incl;      // == NPTS
    }
    if (tid >= 64 && tid < 128) {                // stage mixture constants
        int k = tid - 64;
        smnK[k] = mu[k];
        scfK[k] = g_coef[k];
        saK[k]  = g_a[k];
    }
    __syncthreads();
    if (have) {
        int pos = sbs[mybin] + atomicAdd(&g_cnt[mybin], 1);
        g_xs[pos] = xv;
    }
    gbar();  // B3: g_xs sorted & visible

    // -------- P3: main. One warp per pair of adjacent sorted j's -------------
    // p = w*NBLK + b spreads each block's 32 pairs across the whole density.
    const int p  = w * NBLK + b;                 // 0..4095
    const float xa = g_xs[2 * p];
    const float xb = g_xs[2 * p + 1];
    const float ck = CKDE;

    int ba = max(min((int)((xa - bmn) * invW), nb - 1), 0);
    int bb = max(min((int)((xb - bmn) * invW), nb - 1), 0);
    int blo = min(ba, bb), bhi = max(ba, bb);
    // expand to even indices: extra elements are genuine pairs (reference sums all i)
    int c0 = sbs[max(blo - 2, 0)] & ~1;
    int c1 = (sbs[min(bhi + 3, nb)] + 1) & ~1;

    const float2* xs2 = (const float2*)g_xs;
    float acca = 0.0f, accb = 0.0f;
    #pragma unroll 2
    for (int i = (c0 >> 1) + lane; i < (c1 >> 1); i += 32) {
        float2 v = xs2[i];
        float t;
        t = xa - v.x; acca += ex2(ck * t * t);   // subtraction exact for close pairs
        t = xa - v.y; acca += ex2(ck * t * t);
        t = xb - v.x; accb += ex2(ck * t * t);
        t = xb - v.y; accb += ex2(ck * t * t);
    }

    // mixture pdf partials: 2 components per lane per j
    float d, mixa, mixb;
    d = xa - smnK[lane];      mixa  = scfK[lane]      * ex2(saK[lane]      * d * d);
    d = xa - smnK[lane + 32]; mixa += scfK[lane + 32] * ex2(saK[lane + 32] * d * d);
    d = xb - smnK[lane];      mixb  = scfK[lane]      * ex2(saK[lane]      * d * d);
    d = xb - smnK[lane + 32]; mixb += scfK[lane + 32] * ex2(saK[lane + 32] * d * d);

    // linear combine before reduction: sum_lanes(mix_part - NORM*acc_part) = diff_j
    float ta = mixa - NORM * acca;
    float tb = mixb - NORM * accb;
    #pragma unroll
    for (int o = 16; o > 0; o >>= 1) {
        ta += __shfl_xor_sync(0xffffffffu, ta, o);
        tb += __shfl_xor_sync(0xffffffffu, tb, o);
    }
    if (lane == 0) wsum[w] = ta * ta + tb * tb;
    __syncthreads();
    if (w == 0) {
        float v = wsum[lane];
        #pragma unroll
        for (int o = 16; o > 0; o >>= 1) v += __shfl_xor_sync(0xffffffffu, v, o);
        if (lane == 0) g_bsum[b] = v;
    }
    gbar();  // B4: all block sums visible

    // -------- P4: final reduction by block 0, warp 0 -------------------------
    if (b == 0 && w == 0) {
        float v = 0.0f;
        #pragma unroll
        for (int q = lane; q < NBLK; q += 32) v += g_bsum[q];
        #pragma unroll
        for (int o = 16; o > 0; o >>= 1) v += __shfl_xor_sync(0xffffffffu, v, o);
        if (lane == 0) out[0] = v;
    }
}

extern "C" void kernel_launch(void* const* d_in, const int* in_sizes, int n_in,
                              void* d_out, int out_size) {
    const float* x  = (const float*)d_in[0];  // [8192]
    const float* wl = (const float*)d_in[1];  // [64] weight_logits
    const float* mu = (const float*)d_in[2];  // [64] means
    const float* lv = (const float*)d_in[3];  // [64] log_vars
    float* out = (float*)d_out;

    gmm_fused<<<NBLK, NTHR>>>(x, wl, mu, lv, out);
}

// round 8
// speedup vs baseline: 1.0917x; 1.0917x over previous
#include <cuda_runtime.h>
#include <cuda_bf16.h>
#include <math_constants.h>

// Problem constants
#define NPTS    8192
#define KCOMP   64
#define NB_MAX  256          // max bins
#define MBLK    256          // main blocks
#define WPB     8            // warps per main block
#define GRPS    (MBLK * WPB) // 2048 groups x 4 j's = 8192

// KDE: bw = 0.5*128/8192 = 2^-7 exactly  ->  exp(-8192*d^2) = exp2(CKDE*d^2)
#define LOG2E 1.4426950408889634
__device__ __constant__ float CKDE = (float)(-8192.0 * LOG2E);
__device__ __constant__ float NORM = (float)(1.0 / (2.5066282746310002 * 0.0078125 * 8192.0));
// ex2.ftz flushes to 0 for arg < -126  ->  |d| > 0.10327 contributes exactly 0.
#define HALF_R 0.052f        // bin width >= R/2; window [b-2, b+3) covers +/-R

// Scratch (device globals — no allocation allowed)
__device__ __align__(16) float g_xs[NPTS];   // x counting-sorted by bin
__device__ int   g_binstart[NB_MAX + 1];     // exclusive-scan offsets; [nb..NB_MAX]=NPTS
__device__ int   g_nb;
__device__ float g_mn, g_invW;
__device__ float g_coef[KCOMP];              // w_k / sqrt(2*pi*var_k)
__device__ float g_a[KCOMP];                 // -0.5*log2e / var_k
__device__ float g_bsum[MBLK];
__device__ int   g_ticket = 0;               // self-resets each call

__device__ __forceinline__ float ex2(float x) {
    float r;
    asm("ex2.approx.ftz.f32 %0, %1;" : "=f"(r) : "f"(x));
    return r;
}

// ---------------------------------------------------------------------------
// 1) Prep: min/max (shfl), histogram, warp-parallel scan, counting-sort
//    scatter, softmax constants. One block, 1024 threads, 8 elems/thread.
//    (Identical to the R6 version that passed at rel_err 1.8e-7.)
// ---------------------------------------------------------------------------
__global__ __launch_bounds__(1024) void gmm_prep(const float* __restrict__ x,
                                                 const float* __restrict__ wl,
                                                 const float* __restrict__ lv) {
    __shared__ float wmn[32], wmx[32];
    __shared__ int   h[NB_MAX];
    __shared__ int   bs[NB_MAX + 1];
    __shared__ int   cur[NB_MAX];
    __shared__ float s_mn, s_invW;
    __shared__ int   s_nb;

    int t = threadIdx.x, lane = t & 31, wid = t >> 5;

    float xv[8];
    float mn = CUDART_INF_F, mx = -CUDART_INF_F;
    #pragma unroll
    for (int e = 0; e < 8; e++) {
        float v = x[t + e * 1024];
        xv[e] = v;
        mn = fminf(mn, v);
        mx = fmaxf(mx, v);
    }
    #pragma unroll
    for (int o = 16; o > 0; o >>= 1) {
        mn = fminf(mn, __shfl_xor_sync(0xffffffffu, mn, o));
        mx = fmaxf(mx, __shfl_xor_sync(0xffffffffu, mx, o));
    }
    if (lane == 0) { wmn[wid] = mn; wmx[wid] = mx; }
    if (t < NB_MAX) h[t] = 0;
    __syncthreads();
    if (t < 32) {
        float a = wmn[t], b = wmx[t];
        #pragma unroll
        for (int o = 16; o > 0; o >>= 1) {
            a = fminf(a, __shfl_xor_sync(0xffffffffu, a, o));
            b = fmaxf(b, __shfl_xor_sync(0xffffffffu, b, o));
        }
        if (t == 0) {
            float range = b - a;
            int nb = (range > HALF_R) ? (int)(range / HALF_R) : 1; // floor => W >= R/2
            nb = min(nb, NB_MAX);
            if (nb < 1) nb = 1;
            float invW = (range > 0.0f) ? (float)nb / range : 0.0f;
            s_nb = nb; s_mn = a; s_invW = invW;
            g_nb = nb; g_mn = a; g_invW = invW;
        }
    }
    __syncthreads();

    int   nb   = s_nb;
    float bmn  = s_mn;
    float invW = s_invW;

    int bidx[8];
    #pragma unroll
    for (int e = 0; e < 8; e++) {
        int b = (int)((xv[e] - bmn) * invW);
        b = min(b, nb - 1);
        b = max(b, 0);
        bidx[e] = b;
        atomicAdd(&h[b], 1);
    }
    __syncthreads();

    // Warp 0 scans all 256 bins: 8 bins/lane serial + shfl inclusive scan.
    if (t < 32) {
        int v[8], p[8], run = 0;
        #pragma unroll
        for (int k = 0; k < 8; k++) {
            v[k] = h[t * 8 + k];
            p[k] = run;
            run += v[k];
        }
        int incl = run;
        #pragma unroll
        for (int o = 1; o < 32; o <<= 1) {
            int u = __shfl_up_sync(0xffffffffu, incl, o);
            if (lane >= o) incl += u;
        }
        int excl = incl - run;
        #pragma unroll
        for (int k = 0; k < 8; k++) bs[t * 8 + k] = excl + p[k];
        if (t == 31) bs[NB_MAX] = incl;   // == NPTS
    }
    __syncthreads();

    if (t <= NB_MAX) g_binstart[t] = bs[t];
    if (t < NB_MAX)  cur[t] = bs[t];
    __syncthreads();

    #pragma unroll
    for (int e = 0; e < 8; e++) {
        int pos = atomicAdd(&cur[bidx[e]], 1);
        g_xs[pos] = xv[e];
    }

    // softmax + per-component constants (direct global reads -> race-free)
    if (t < KCOMP) {
        float m = -CUDART_INF_F;
        #pragma unroll
        for (int i = 0; i < KCOMP; i++) m = fmaxf(m, __ldg(&wl[i]));
        float ssum = 0.0f;
        #pragma unroll
        for (int i = 0; i < KCOMP; i++) ssum += __expf(__ldg(&wl[i]) - m);
        float w   = __expf(__ldg(&wl[t]) - m) / ssum;
        float var = __expf(lv[t]);
        g_coef[t] = w * rsqrtf(6.283185307179586f * var);
        g_a[t]    = (float)(-0.5 * LOG2E) / var;
    }
}

// ---------------------------------------------------------------------------
// 2) Main: one warp per 4 ADJACENT sorted j's (counting sort => their bins
//    are ordered, one shared window covers all four). Lanes stride the window
//    with float2 loads: 8 exps / 8 bytes, 4 independent accumulators (MUFU ILP).
//    Group id g = w*MBLK + blockIdx.x spreads each block across the density.
// ---------------------------------------------------------------------------
__global__ __launch_bounds__(256) void gmm_main(const float* __restrict__ means,
                                                float* __restrict__ out) {
    __shared__ float smn[KCOMP], scf[KCOMP], sa[KCOMP];
    __shared__ float wsum[WPB];
    __shared__ float rs[256];
    __shared__ int   s_last;

    int tid = threadIdx.x, lane = tid & 31, w = tid >> 5;
    if (tid < KCOMP) {
        smn[tid] = means[tid];
        scf[tid] = g_coef[tid];
        sa[tid]  = g_a[tid];
    }
    __syncthreads();

    const int g = w * MBLK + blockIdx.x;              // 0..2047
    const float4 xj4 = *(const float4*)&g_xs[4 * g];  // 16B-aligned
    const float xa = xj4.x, xb = xj4.y, xc = xj4.z, xd = xj4.w;

    const int   nb   = g_nb;
    const float bmn  = g_mn;
    const float invW = g_invW;
    int blo = max(min((int)((xa - bmn) * invW), nb - 1), 0);   // first j's bin
    int bhi = max(min((int)((xd - bmn) * invW), nb - 1), 0);   // last j's bin (>= blo)
    int c0 = __ldg(&g_binstart[max(blo - 2, 0)]) & ~1;
    int c1 = (__ldg(&g_binstart[min(bhi + 3, nb)]) + 1) & ~1;
    // even-rounding adds genuine pairs (reference sums all i; far terms flush to 0)

    const float ck = CKDE;
    const float2* xs2 = (const float2*)g_xs;
    float A = 0.0f, B = 0.0f, C = 0.0f, D = 0.0f;
    #pragma unroll 2
    for (int i = (c0 >> 1) + lane; i < (c1 >> 1); i += 32) {
        float2 v = xs2[i];
        float t;
        t = xa - v.x; A += ex2(ck * t * t);   // subtraction exact for close pairs
        t = xa - v.y; A += ex2(ck * t * t);
        t = xb - v.x; B += ex2(ck * t * t);
        t = xb - v.y; B += ex2(ck * t * t);
        t = xc - v.x; C += ex2(ck * t * t);
        t = xc - v.y; C += ex2(ck * t * t);
        t = xd - v.x; D += ex2(ck * t * t);
        t = xd - v.y; D += ex2(ck * t * t);
    }

    // mixture pdf partials: 2 components per lane per j
    float d, ma, mb, mc, md;
    d = xa - smn[lane];      ma  = scf[lane]      * ex2(sa[lane]      * d * d);
    d = xa - smn[lane + 32]; ma += scf[lane + 32] * ex2(sa[lane + 32] * d * d);
    d = xb - smn[lane];      mb  = scf[lane]      * ex2(sa[lane]      * d * d);
    d = xb - smn[lane + 32]; mb += scf[lane + 32] * ex2(sa[lane + 32] * d * d);
    d = xc - smn[lane];      mc  = scf[lane]      * ex2(sa[lane]      * d * d);
    d = xc - smn[lane + 32]; mc += scf[lane + 32] * ex2(sa[lane + 32] * d * d);
    d = xd - smn[lane];      md  = scf[lane]      * ex2(sa[lane]      * d * d);
    d = xd - smn[lane + 32]; md += scf[lane + 32] * ex2(sa[lane + 32] * d * d);

    // linear combine before reduction: sum_lanes(mix_part - NORM*acc_part) = diff_j
    float ta = ma - NORM * A;
    float tb = mb - NORM * B;
    float tc = mc - NORM * C;
    float td = md - NORM * D;
    #pragma unroll
    for (int o = 16; o > 0; o >>= 1) {
        ta += __shfl_xor_sync(0xffffffffu, ta, o);
        tb += __shfl_xor_sync(0xffffffffu, tb, o);
        tc += __shfl_xor_sync(0xffffffffu, tc, o);
        td += __shfl_xor_sync(0xffffffffu, td, o);
    }
    if (lane == 0) wsum[w] = ta * ta + tb * tb + tc * tc + td * td;
    __syncthreads();

    if (tid == 0) {
        float v = 0.0f;
        #pragma unroll
        for (int p = 0; p < WPB; p++) v += wsum[p];
        g_bsum[blockIdx.x] = v;
        __threadfence();
        int tk = atomicAdd(&g_ticket, 1);
        s_last = (tk == MBLK - 1);
    }
    __syncthreads();

    if (s_last) {
        __threadfence();                     // acquire: order reads after ticket
        rs[tid] = g_bsum[tid];
        __syncthreads();
        #pragma unroll
        for (int off = 128; off > 0; off >>= 1) {
            if (tid < off) rs[tid] += rs[tid + off];
            __syncthreads();
        }
        if (tid == 0) {
            out[0] = rs[0];
            g_ticket = 0;   // reset for next graph replay
        }
    }
}

extern "C" void kernel_launch(void* const* d_in, const int* in_sizes, int n_in,
                              void* d_out, int out_size) {
    const float* x  = (const float*)d_in[0];  // [8192]
    const float* wl = (const float*)d_in[1];  // [64] weight_logits
    const float* mu = (const float*)d_in[2];  // [64] means
    const float* lv = (const float*)d_in[3];  // [64] log_vars
    float* out = (float*)d_out;

    gmm_prep<<<1, 1024>>>(x, wl, lv);
    gmm_main<<<MBLK, 256>>>(mu, out);
}